// round 3
// baseline (speedup 1.0000x reference)
#include <cuda_runtime.h>
#include <cuda_fp16.h>
#include <cuda_bf16.h>
#include <mma.h>

using namespace nvcuda;

// Problem dims (fixed by the dataset)
#define T_ROWS 16384
#define D_IN   1024
#define D_MID  4096
#define D_OUT  1024

// -------- scratch (static device globals; no allocs allowed) --------
__device__ __half g_XR[(size_t)T_ROWS * D_IN];    // rotated x, fp16
__device__ __half g_W1[(size_t)D_MID * D_IN];     // up_wq fp16
__device__ __half g_W2[(size_t)D_OUT * D_MID];    // down_wq fp16
__device__ __half g_A [(size_t)T_ROWS * D_MID];   // gelu(h)*down_signs fp16
__device__ __half g_AR[(size_t)T_ROWS * D_MID];   // rotated activation fp16

// -------- fp32 -> fp16 convert --------
__global__ void f32_to_f16_kernel(const float* __restrict__ in, __half* __restrict__ out, int n) {
    int i = blockIdx.x * blockDim.x + threadIdx.x;
    int stride = gridDim.x * blockDim.x;
    for (; i < n; i += stride) out[i] = __float2half(in[i]);
}

// -------- RHT: x*signs then FWHT-128, orthonormal, fp32 in -> fp16 out --------
// One warp per 128-chunk; 8 warps per block. Shuffle butterflies (no smem/bars).
__global__ void rht_f32_kernel(const float* __restrict__ x, const float* __restrict__ signs,
                               __half* __restrict__ out, int D) {
    int warp = blockIdx.x * 8 + (threadIdx.x >> 5);
    int lane = threadIdx.x & 31;
    size_t base = (size_t)warp * 128;
    int colbase = (int)(base % (size_t)D);
    float v[4];
#pragma unroll
    for (int j = 0; j < 4; j++) {
        int idx = lane + 32 * j;
        v[j] = x[base + idx] * signs[colbase + idx];
    }
#pragma unroll
    for (int len = 1; len <= 16; len <<= 1) {
#pragma unroll
        for (int j = 0; j < 4; j++) {
            float o = __shfl_xor_sync(0xffffffffu, v[j], len);
            v[j] = (lane & len) ? (o - v[j]) : (v[j] + o);
        }
    }
    // len = 32 and 64 are in-thread
    float t0 = v[0] + v[1], t1 = v[0] - v[1], t2 = v[2] + v[3], t3 = v[2] - v[3];
    v[0] = t0 + t2; v[2] = t0 - t2; v[1] = t1 + t3; v[3] = t1 - t3;
    const float nrm = 0.08838834764831845f; // 1/sqrt(128)
#pragma unroll
    for (int j = 0; j < 4; j++)
        out[base + lane + 32 * j] = __float2half(v[j] * nrm);
}

// -------- pure FWHT-128 on fp16 data (signs already applied) --------
__global__ void fwht_f16_kernel(const __half* __restrict__ in, __half* __restrict__ out) {
    int warp = blockIdx.x * 8 + (threadIdx.x >> 5);
    int lane = threadIdx.x & 31;
    size_t base = (size_t)warp * 128;
    float v[4];
#pragma unroll
    for (int j = 0; j < 4; j++) v[j] = __half2float(in[base + lane + 32 * j]);
#pragma unroll
    for (int len = 1; len <= 16; len <<= 1) {
#pragma unroll
        for (int j = 0; j < 4; j++) {
            float o = __shfl_xor_sync(0xffffffffu, v[j], len);
            v[j] = (lane & len) ? (o - v[j]) : (v[j] + o);
        }
    }
    float t0 = v[0] + v[1], t1 = v[0] - v[1], t2 = v[2] + v[3], t3 = v[2] - v[3];
    v[0] = t0 + t2; v[2] = t0 - t2; v[1] = t1 + t3; v[3] = t1 - t3;
    const float nrm = 0.08838834764831845f;
#pragma unroll
    for (int j = 0; j < 4; j++)
        out[base + lane + 32 * j] = __float2half(v[j] * nrm);
}

// -------- GEMM: C[m,n] = sum_k A[m,k]*B[n,k]  (A,B fp16 K-major; fp32 accum) --------
// BM=BN=128, BK=32, 8 warps, warp tile 32x64 (2x4 wmma 16x16x16 frags).
// GELU=true : out fp16 = gelu(acc*scale[n]) * signs[n]   (GEMM1 fused epilogue)
// GELU=false: out fp32 = acc*scale[n]                    (GEMM2)
template <bool GELU>
__global__ __launch_bounds__(256, 1)
void gemm_e8_kernel(const __half* __restrict__ A, const __half* __restrict__ B,
                    const float* __restrict__ scale, const float* __restrict__ signs,
                    void* __restrict__ Cout, int M, int N, int K) {
    constexpr int BK = 32;
    constexpr int LDS = 48;   // half elements per row: 96B, multiple of 16B
    constexpr int LDC = 20;   // float elements per row: 80B, multiple of 16B (wmma requirement)
    __shared__ __half As[128][LDS];
    __shared__ __half Bs[128][LDS];
    __shared__ float  sc[8][16 * LDC];

    int tid = threadIdx.x;
    int w = tid >> 5, lane = tid & 31;
    int wm = (w & 3) * 32;       // warp m offset (4 warps along M)
    int wn = (w >> 2) * 64;      // warp n offset (2 warps along N)
    int m0 = blockIdx.y * 128;
    int n0 = blockIdx.x * 128;

    wmma::fragment<wmma::accumulator, 16, 16, 16, float> acc[2][4];
#pragma unroll
    for (int i = 0; i < 2; i++)
#pragma unroll
        for (int j = 0; j < 4; j++) wmma::fill_fragment(acc[i][j], 0.0f);

    for (int k0 = 0; k0 < K; k0 += BK) {
        // load 128x32 tiles, vectorized 16B
#pragma unroll
        for (int v = tid; v < 512; v += 256) {
            int r = v >> 2, c = v & 3;
            *reinterpret_cast<uint4*>(&As[r][c * 8]) =
                *reinterpret_cast<const uint4*>(A + (size_t)(m0 + r) * K + k0 + c * 8);
        }
#pragma unroll
        for (int v = tid; v < 512; v += 256) {
            int r = v >> 2, c = v & 3;
            *reinterpret_cast<uint4*>(&Bs[r][c * 8]) =
                *reinterpret_cast<const uint4*>(B + (size_t)(n0 + r) * K + k0 + c * 8);
        }
        __syncthreads();

#pragma unroll
        for (int kk = 0; kk < BK; kk += 16) {
            wmma::fragment<wmma::matrix_a, 16, 16, 16, __half, wmma::row_major> af[2];
            wmma::fragment<wmma::matrix_b, 16, 16, 16, __half, wmma::col_major> bf[4];
#pragma unroll
            for (int i = 0; i < 2; i++)
                wmma::load_matrix_sync(af[i], &As[wm + i * 16][kk], LDS);
#pragma unroll
            for (int j = 0; j < 4; j++)
                wmma::load_matrix_sync(bf[j], &Bs[wn + j * 16][kk], LDS);
#pragma unroll
            for (int i = 0; i < 2; i++)
#pragma unroll
                for (int j = 0; j < 4; j++)
                    wmma::mma_sync(acc[i][j], af[i], bf[j], acc[i][j]);
        }
        __syncthreads();
    }

    // epilogue via per-warp smem scratch
    float* myc = sc[w];
#pragma unroll
    for (int i = 0; i < 2; i++) {
#pragma unroll
        for (int j = 0; j < 4; j++) {
            wmma::store_matrix_sync(myc, acc[i][j], LDC, wmma::mem_row_major);
            __syncwarp();
            int row0 = m0 + wm + i * 16;
            int col0 = n0 + wn + j * 16;
#pragma unroll
            for (int e = lane * 8; e < lane * 8 + 8; e++) {
                int r = e >> 4, c = e & 15;
                int col = col0 + c;
                float v = myc[r * LDC + c] * scale[col];
                if (GELU) {
                    float u = 0.7978845608028654f * (v + 0.044715f * v * v * v);
                    v = 0.5f * v * (1.0f + tanhf(u));
                    v *= signs[col];
                    reinterpret_cast<__half*>(Cout)[(size_t)(row0 + r) * N + col] = __float2half(v);
                } else {
                    reinterpret_cast<float*>(Cout)[(size_t)(row0 + r) * N + col] = v;
                }
            }
            __syncwarp();
        }
    }
}

extern "C" void kernel_launch(void* const* d_in, const int* in_sizes, int n_in,
                              void* d_out, int out_size) {
    const float* x          = (const float*)d_in[0];
    const float* up_wq      = (const float*)d_in[1];
    const float* up_scale   = (const float*)d_in[2];
    const float* down_wq    = (const float*)d_in[3];
    const float* down_scale = (const float*)d_in[4];
    const float* up_signs   = (const float*)d_in[5];
    const float* down_signs = (const float*)d_in[6];

    __half *pXR, *pW1, *pW2, *pA, *pAR;
    { void* p; cudaGetSymbolAddress(&p, g_XR); pXR = (__half*)p; }
    { void* p; cudaGetSymbolAddress(&p, g_W1); pW1 = (__half*)p; }
    { void* p; cudaGetSymbolAddress(&p, g_W2); pW2 = (__half*)p; }
    { void* p; cudaGetSymbolAddress(&p, g_A ); pA  = (__half*)p; }
    { void* p; cudaGetSymbolAddress(&p, g_AR); pAR = (__half*)p; }

    // 1) weight converts
    f32_to_f16_kernel<<<2048, 256>>>(up_wq,   pW1, D_MID * D_IN);
    f32_to_f16_kernel<<<2048, 256>>>(down_wq, pW2, D_OUT * D_MID);

    // 2) RHT(x, up_signs) -> XR (fp16)
    {
        int chunks = T_ROWS * (D_IN / 128);   // 131072
        rht_f32_kernel<<<chunks / 8, 256>>>(x, up_signs, pXR, D_IN);
    }

    // 3) GEMM1 + fused scale/gelu/down_signs -> A (fp16)
    {
        dim3 grid(D_MID / 128, T_ROWS / 128); // (32, 128)
        gemm_e8_kernel<true><<<grid, 256>>>(pXR, pW1, up_scale, down_signs, pA,
                                            T_ROWS, D_MID, D_IN);
    }

    // 4) FWHT on activation -> AR (fp16)
    {
        int chunks = T_ROWS * (D_MID / 128);  // 524288
        fwht_f16_kernel<<<chunks / 8, 256>>>(pA, pAR);
    }

    // 5) GEMM2 + down_scale -> out (fp32)
    {
        dim3 grid(D_OUT / 128, T_ROWS / 128); // (8, 128)
        gemm_e8_kernel<false><<<grid, 256>>>(pAR, pW2, down_scale, nullptr, d_out,
                                             T_ROWS, D_OUT, D_MID);
    }
}

// round 5
// speedup vs baseline: 1.4030x; 1.4030x over previous
#include <cuda_runtime.h>
#include <cuda_fp16.h>
#include <cstdint>

#define T_ROWS 16384
#define D_IN   1024
#define D_MID  4096
#define D_OUT  1024

// GEMM tiling
#define BM 256
#define BN 128
#define BK 32
#define STAGES 3
#define SAH 40                     // smem row stride in halves (80B, 16B-mult, conflict-free)
#define A_ST (BM * SAH * 2)        // 20480 B
#define B_ST (BN * SAH * 2)        // 10240 B
#define STG_BYTES (A_ST + B_ST)    // 30720 B
#define DYN_SMEM (STAGES * STG_BYTES + 1024)

// -------- scratch (static device globals; no allocs allowed) --------
__device__ __half g_XR[(size_t)T_ROWS * D_IN];
__device__ __half g_W1[(size_t)D_MID * D_IN];
__device__ __half g_W2[(size_t)D_OUT * D_MID];
__device__ __half g_AR[(size_t)T_ROWS * D_MID];

// ---------------- helpers ----------------
static __device__ __forceinline__ uint32_t s2u(const void* p) {
    return (uint32_t)__cvta_generic_to_shared(p);
}
static __device__ __forceinline__ void cp16(uint32_t dst, const void* src) {
    asm volatile("cp.async.cg.shared.global [%0], [%1], 16;" :: "r"(dst), "l"(src));
}
static __device__ __forceinline__ void cp_commit() { asm volatile("cp.async.commit_group;" ::: "memory"); }
template <int N>
static __device__ __forceinline__ void cp_wait() { asm volatile("cp.async.wait_group %0;" :: "n"(N) : "memory"); }

static __device__ __forceinline__ void ldsm_x4(uint32_t& r0, uint32_t& r1, uint32_t& r2, uint32_t& r3,
                                               uint32_t addr) {
    asm volatile("ldmatrix.sync.aligned.m8n8.x4.shared.b16 {%0,%1,%2,%3}, [%4];"
                 : "=r"(r0), "=r"(r1), "=r"(r2), "=r"(r3) : "r"(addr));
}
static __device__ __forceinline__ void mma16816(float* c, const uint32_t* a, const uint32_t* b) {
    asm volatile(
        "mma.sync.aligned.m16n8k16.row.col.f32.f16.f16.f32 "
        "{%0,%1,%2,%3}, {%4,%5,%6,%7}, {%8,%9}, {%0,%1,%2,%3};"
        : "+f"(c[0]), "+f"(c[1]), "+f"(c[2]), "+f"(c[3])
        : "r"(a[0]), "r"(a[1]), "r"(a[2]), "r"(a[3]), "r"(b[0]), "r"(b[1]));
}
static __device__ __forceinline__ float gelu_f(float v) {
    float t = 1.5957691216057308f * (v + 0.044715f * v * v * v);
    return v * (1.0f / (1.0f + __expf(-t)));
}

// -------- fp32 -> fp16 convert --------
__global__ void f32_to_f16_kernel(const float* __restrict__ in, __half* __restrict__ out, int n) {
    int i = blockIdx.x * blockDim.x + threadIdx.x;
    int stride = gridDim.x * blockDim.x;
    for (; i < n; i += stride) out[i] = __float2half(in[i]);
}

// -------- RHT: x*signs then FWHT-128, fp32 in -> fp16 out --------
__global__ void rht_f32_kernel(const float* __restrict__ x, const float* __restrict__ signs,
                               __half* __restrict__ out, int D) {
    int warp = blockIdx.x * 8 + (threadIdx.x >> 5);
    int lane = threadIdx.x & 31;
    size_t base = (size_t)warp * 128;
    int colbase = (int)(base % (size_t)D);
    float v[4];
#pragma unroll
    for (int j = 0; j < 4; j++) {
        int idx = lane + 32 * j;
        v[j] = x[base + idx] * signs[colbase + idx];
    }
#pragma unroll
    for (int len = 1; len <= 16; len <<= 1) {
#pragma unroll
        for (int j = 0; j < 4; j++) {
            float o = __shfl_xor_sync(0xffffffffu, v[j], len);
            v[j] = (lane & len) ? (o - v[j]) : (v[j] + o);
        }
    }
    float t0 = v[0] + v[1], t1 = v[0] - v[1], t2 = v[2] + v[3], t3 = v[2] - v[3];
    v[0] = t0 + t2; v[2] = t0 - t2; v[1] = t1 + t3; v[3] = t1 - t3;
    const float nrm = 0.08838834764831845f;
#pragma unroll
    for (int j = 0; j < 4; j++)
        out[base + lane + 32 * j] = __float2half(v[j] * nrm);
}

// ================= HMMA GEMM =================
// C[m,n] = sum_k A[m,k]*B[n,k]; A:[M,K], B:[N,K] fp16 K-major.
// 512 threads, warp grid 4(M)x4(N), warp tile 64x32, mma.m16n8k16.
// MODE 0: gelu(acc*scale[n])*signs[n], FWHT-128 along n, fp16 out.
// MODE 1: acc*scale[n], fp32 out.
template <int MODE>
__global__ __launch_bounds__(512, 1)
void gemm_mma(const __half* __restrict__ A, const __half* __restrict__ B,
              const float* __restrict__ scale, const float* __restrict__ signs,
              void* __restrict__ Out, int M, int Nfull, int K) {
    extern __shared__ char dsm_raw[];
    char* sb = (char*)((((uintptr_t)dsm_raw) + 1023) & ~(uintptr_t)1023);
    const uint32_t sbase = s2u(sb);

    const int tid = threadIdx.x;
    const int wid = tid >> 5;
    const int lane = tid & 31;
    const int wm = (wid >> 2) * 64;   // warp m offset
    const int wn = (wid & 3) * 32;    // warp n offset
    const int m0 = blockIdx.y * BM;
    const int n0 = blockIdx.x * BN;
    const int KI = K / BK;

    float acc[4][4][4];
#pragma unroll
    for (int i = 0; i < 4; i++)
#pragma unroll
        for (int j = 0; j < 4; j++)
#pragma unroll
            for (int e = 0; e < 4; e++) acc[i][j][e] = 0.0f;

    auto load_stage = [&](int s, int kk) {
        const int k0 = kk * BK;
        uint32_t aB = sbase + s * STG_BYTES;
        uint32_t bB = aB + A_ST;
        const __half* Ap = A + (size_t)m0 * K + k0;
        const __half* Bp = B + (size_t)n0 * K + k0;
#pragma unroll
        for (int i = 0; i < 2; i++) {   // A: 256 rows x 4 chunks = 1024
            int idx = tid + i * 512;
            int row = idx >> 2, c = idx & 3;
            cp16(aB + (uint32_t)(row * (SAH * 2) + c * 16), Ap + (size_t)row * K + c * 8);
        }
        {                               // B: 128 rows x 4 chunks = 512
            int row = tid >> 2, c = tid & 3;
            cp16(bB + (uint32_t)(row * (SAH * 2) + c * 16), Bp + (size_t)row * K + c * 8);
        }
    };

    // prologue
    load_stage(0, 0); cp_commit();
    if (KI > 1) load_stage(1, 1);
    cp_commit();

    for (int k = 0; k < KI; k++) {
        cp_wait<1>();
        __syncthreads();
        if (k + 2 < KI) load_stage((k + 2) % 3, k + 2);
        cp_commit();

        const uint32_t sA = sbase + (k % 3) * STG_BYTES;
        const uint32_t sB = sA + A_ST;
#pragma unroll
        for (int ks = 0; ks < 2; ks++) {
            uint32_t a[4][4], b[4][2];
#pragma unroll
            for (int i = 0; i < 4; i++) {
                uint32_t addr = sA + (uint32_t)(((wm + i * 16 + (lane & 15)) * SAH
                                  + ks * 16 + ((lane >> 4) << 3)) * 2);
                ldsm_x4(a[i][0], a[i][1], a[i][2], a[i][3], addr);
            }
#pragma unroll
            for (int p = 0; p < 2; p++) {
                uint32_t addr = sB + (uint32_t)(((wn + p * 16 + ((lane >> 4) << 3) + (lane & 7)) * SAH
                                  + ks * 16 + (lane & 8)) * 2);
                ldsm_x4(b[2 * p][0], b[2 * p][1], b[2 * p + 1][0], b[2 * p + 1][1], addr);
            }
#pragma unroll
            for (int i = 0; i < 4; i++)
#pragma unroll
                for (int j = 0; j < 4; j++)
                    mma16816(acc[i][j], a[i], b[j]);
        }
    }

    cp_wait<0>();
    __syncthreads();

    // ---------------- epilogue ----------------
    if (MODE == 0) {
        // stage gelu output (fp16) in smem, FWHT-128 along n, write fp16
        const int EST = 136;  // half stride
        __half* Es = (__half*)sb;
#pragma unroll
        for (int i = 0; i < 4; i++) {
#pragma unroll
            for (int j = 0; j < 4; j++) {
                int row = wm + i * 16 + (lane >> 2);
                int cl = wn + j * 8 + (lane & 3) * 2;
                int col = n0 + cl;
                float s0 = __ldg(scale + col), s1 = __ldg(scale + col + 1);
                float g0 = __ldg(signs + col), g1 = __ldg(signs + col + 1);
                float v00 = gelu_f(acc[i][j][0] * s0) * g0;
                float v01 = gelu_f(acc[i][j][1] * s1) * g1;
                float v10 = gelu_f(acc[i][j][2] * s0) * g0;
                float v11 = gelu_f(acc[i][j][3] * s1) * g1;
                *(__half2*)&Es[row * EST + cl] = __floats2half2_rn(v00, v01);
                *(__half2*)&Es[(row + 8) * EST + cl] = __floats2half2_rn(v10, v11);
            }
        }
        __syncthreads();
        const float nrm = 0.08838834764831845f;
        for (int r = wid; r < BM; r += 16) {
            float v[4];
#pragma unroll
            for (int j = 0; j < 4; j++) v[j] = __half2float(Es[r * EST + lane + 32 * j]);
#pragma unroll
            for (int len = 1; len <= 16; len <<= 1) {
#pragma unroll
                for (int j = 0; j < 4; j++) {
                    float o = __shfl_xor_sync(0xffffffffu, v[j], len);
                    v[j] = (lane & len) ? (o - v[j]) : (v[j] + o);
                }
            }
            float t0 = v[0] + v[1], t1 = v[0] - v[1], t2 = v[2] + v[3], t3 = v[2] - v[3];
            v[0] = t0 + t2; v[2] = t0 - t2; v[1] = t1 + t3; v[3] = t1 - t3;
            __half* dst = (__half*)Out + (size_t)(m0 + r) * Nfull + n0;
#pragma unroll
            for (int j = 0; j < 4; j++) dst[lane + 32 * j] = __float2half(v[j] * nrm);
        }
    } else {
        // direct register epilogue, fp32 out
#pragma unroll
        for (int i = 0; i < 4; i++) {
#pragma unroll
            for (int j = 0; j < 4; j++) {
                int row = m0 + wm + i * 16 + (lane >> 2);
                int col = n0 + wn + j * 8 + (lane & 3) * 2;
                float s0 = __ldg(scale + col), s1 = __ldg(scale + col + 1);
                float2 lo = make_float2(acc[i][j][0] * s0, acc[i][j][1] * s1);
                float2 hi = make_float2(acc[i][j][2] * s0, acc[i][j][3] * s1);
                *(float2*)((float*)Out + (size_t)row * Nfull + col) = lo;
                *(float2*)((float*)Out + (size_t)(row + 8) * Nfull + col) = hi;
            }
        }
    }
}

// ================= host =================
extern "C" void kernel_launch(void* const* d_in, const int* in_sizes, int n_in,
                              void* d_out, int out_size) {
    const float* x          = (const float*)d_in[0];
    const float* up_wq      = (const float*)d_in[1];
    const float* up_scale   = (const float*)d_in[2];
    const float* down_wq    = (const float*)d_in[3];
    const float* down_scale = (const float*)d_in[4];
    const float* up_signs   = (const float*)d_in[5];
    const float* down_signs = (const float*)d_in[6];

    __half *pXR, *pW1, *pW2, *pAR;
    { void* p; cudaGetSymbolAddress(&p, g_XR); pXR = (__half*)p; }
    { void* p; cudaGetSymbolAddress(&p, g_W1); pW1 = (__half*)p; }
    { void* p; cudaGetSymbolAddress(&p, g_W2); pW2 = (__half*)p; }
    { void* p; cudaGetSymbolAddress(&p, g_AR); pAR = (__half*)p; }

    cudaFuncSetAttribute(gemm_mma<0>, cudaFuncAttributeMaxDynamicSharedMemorySize, DYN_SMEM);
    cudaFuncSetAttribute(gemm_mma<1>, cudaFuncAttributeMaxDynamicSharedMemorySize, DYN_SMEM);

    // 1) weight converts
    f32_to_f16_kernel<<<2048, 256>>>(up_wq,   pW1, D_MID * D_IN);
    f32_to_f16_kernel<<<2048, 256>>>(down_wq, pW2, D_OUT * D_MID);

    // 2) RHT(x, up_signs) -> XR fp16
    rht_f32_kernel<<<(T_ROWS * (D_IN / 128)) / 8, 256>>>(x, up_signs, pXR, D_IN);

    // 3) GEMM1 (+ scale, gelu, down_signs, fused FWHT) -> AR fp16
    {
        dim3 grid(D_MID / BN, T_ROWS / BM);  // (32, 64)
        gemm_mma<0><<<grid, 512, DYN_SMEM>>>(pXR, pW1, up_scale, down_signs, pAR,
                                             T_ROWS, D_MID, D_IN);
    }

    // 4) GEMM2 (+ down_scale) -> out fp32
    {
        dim3 grid(D_OUT / BN, T_ROWS / BM);  // (8, 64)
        gemm_mma<1><<<grid, 512, DYN_SMEM>>>(pAR, pW2, down_scale, nullptr, d_out,
                                             T_ROWS, D_OUT, D_MID);
    }
}

// round 7
// speedup vs baseline: 2.3511x; 1.6757x over previous
#include <cuda_runtime.h>
#include <cuda_fp16.h>
#include <cstdint>

#define T_ROWS 16384
#define D_IN   1024
#define D_MID  4096
#define D_OUT  1024

// GEMM tiling
#define BM 256
#define BN 128
#define BK 64
#define STAGES 3
#define SAH 72                     // smem row stride in halves (144B): conflict-free ldsm
#define A_ST (BM * SAH * 2)        // 36864 B
#define B_ST (BN * SAH * 2)        // 18432 B
#define STG_BYTES (A_ST + B_ST)    // 55296 B
#define DYN_SMEM (STAGES * STG_BYTES + 128)

// -------- scratch (static device globals; no allocs allowed) --------
__device__ __half g_XS[(size_t)T_ROWS * D_IN];    // x * up_signs, fp16
__device__ __half g_W1[(size_t)D_MID * D_IN];     // up_wq * H (blockwise), fp16
__device__ __half g_W2[(size_t)D_OUT * D_MID];    // down_wq * H (blockwise), fp16
__device__ __half g_AR[(size_t)T_ROWS * D_MID];   // gelu(h)*down_signs, fp16

// ---------------- helpers ----------------
static __device__ __forceinline__ uint32_t s2u(const void* p) {
    return (uint32_t)__cvta_generic_to_shared(p);
}
static __device__ __forceinline__ void cp16(uint32_t dst, const void* src) {
    asm volatile("cp.async.cg.shared.global [%0], [%1], 16;" :: "r"(dst), "l"(src));
}
static __device__ __forceinline__ void cp_commit() { asm volatile("cp.async.commit_group;" ::: "memory"); }
template <int N>
static __device__ __forceinline__ void cp_wait() { asm volatile("cp.async.wait_group %0;" :: "n"(N) : "memory"); }

static __device__ __forceinline__ void ldsm_x4(uint32_t& r0, uint32_t& r1, uint32_t& r2, uint32_t& r3,
                                               uint32_t addr) {
    asm volatile("ldmatrix.sync.aligned.m8n8.x4.shared.b16 {%0,%1,%2,%3}, [%4];"
                 : "=r"(r0), "=r"(r1), "=r"(r2), "=r"(r3) : "r"(addr));
}
static __device__ __forceinline__ void mma16816(float* c, const uint32_t* a, const uint32_t* b) {
    asm volatile(
        "mma.sync.aligned.m16n8k16.row.col.f32.f16.f16.f32 "
        "{%0,%1,%2,%3}, {%4,%5,%6,%7}, {%8,%9}, {%0,%1,%2,%3};"
        : "+f"(c[0]), "+f"(c[1]), "+f"(c[2]), "+f"(c[3])
        : "r"(a[0]), "r"(a[1]), "r"(a[2]), "r"(a[3]), "r"(b[0]), "r"(b[1]));
}
static __device__ __forceinline__ float gelu_f(float v) {
    float t = 1.5957691216057308f * (v + 0.044715f * v * v * v);
    return v * (1.0f / (1.0f + __expf(-t)));
}

// -------- W' = W * H (blockwise FWHT along contiguous dim), fp32 -> fp16 --------
__global__ void fwht_w_kernel(const float* __restrict__ w, __half* __restrict__ out) {
    int warp = blockIdx.x * 8 + (threadIdx.x >> 5);
    int lane = threadIdx.x & 31;
    size_t base = (size_t)warp * 128;
    float v[4];
#pragma unroll
    for (int j = 0; j < 4; j++) v[j] = w[base + lane + 32 * j];
#pragma unroll
    for (int len = 1; len <= 16; len <<= 1) {
#pragma unroll
        for (int j = 0; j < 4; j++) {
            float o = __shfl_xor_sync(0xffffffffu, v[j], len);
            v[j] = (lane & len) ? (o - v[j]) : (v[j] + o);
        }
    }
    float t0 = v[0] + v[1], t1 = v[0] - v[1], t2 = v[2] + v[3], t3 = v[2] - v[3];
    v[0] = t0 + t2; v[2] = t0 - t2; v[1] = t1 + t3; v[3] = t1 - t3;
    const float nrm = 0.08838834764831845f;
#pragma unroll
    for (int j = 0; j < 4; j++)
        out[base + lane + 32 * j] = __float2half(v[j] * nrm);
}

// -------- XS = x * up_signs, fp32 -> fp16 (vectorized) --------
__global__ void xs_kernel(const float* __restrict__ x, const float* __restrict__ signs,
                          __half* __restrict__ out) {
    int i = blockIdx.x * blockDim.x + threadIdx.x;   // one float4 per thread
    float4 v = reinterpret_cast<const float4*>(x)[i];
    int col = (i * 4) & (D_IN - 1);
    float4 s = *reinterpret_cast<const float4*>(signs + col);
    __half2 h0 = __floats2half2_rn(v.x * s.x, v.y * s.y);
    __half2 h1 = __floats2half2_rn(v.z * s.z, v.w * s.w);
    reinterpret_cast<__half2*>(out)[2 * i]     = h0;
    reinterpret_cast<__half2*>(out)[2 * i + 1] = h1;
}

// ================= HMMA GEMM =================
// C[m,n] = sum_k A[m,k]*B[n,k]; A:[M,K], B:[N,K] fp16 K-major.
// 256 threads, warp grid 4(M)x2(N), warp tile 64x64, mma.m16n8k16, BK=64,
// double-buffered register fragments.
// MODE 0: out fp16 = gelu(acc*scale[n]) * signs[n]   (register epilogue)
// MODE 1: out fp32 = acc*scale[n]
template <int MODE>
__global__ __launch_bounds__(256, 1)
void gemm_mma(const __half* __restrict__ A, const __half* __restrict__ B,
              const float* __restrict__ scale, const float* __restrict__ signs,
              void* __restrict__ Out, int M, int Nfull, int K) {
    extern __shared__ char dsm_raw[];
    char* sb = (char*)((((uintptr_t)dsm_raw) + 127) & ~(uintptr_t)127);
    const uint32_t sbase = s2u(sb);

    const int tid = threadIdx.x;
    const int wid = tid >> 5;
    const int lane = tid & 31;
    const int wm = (wid >> 1) * 64;   // 4 warps along M
    const int wn = (wid & 1) * 64;    // 2 warps along N
    const int m0 = blockIdx.y * BM;
    const int n0 = blockIdx.x * BN;
    const int KI = K / BK;

    float acc[4][8][4];
#pragma unroll
    for (int i = 0; i < 4; i++)
#pragma unroll
        for (int j = 0; j < 8; j++)
#pragma unroll
            for (int e = 0; e < 4; e++) acc[i][j][e] = 0.0f;

    auto load_stage = [&](int s, int kk) {
        const int k0 = kk * BK;
        uint32_t aB = sbase + s * STG_BYTES;
        uint32_t bB = aB + A_ST;
        const __half* Ap = A + (size_t)m0 * K + k0;
        const __half* Bp = B + (size_t)n0 * K + k0;
#pragma unroll
        for (int i = 0; i < 8; i++) {   // A: 256 rows x 8 chunks of 16B
            int idx = tid + i * 256;
            int row = idx >> 3, c = idx & 7;
            cp16(aB + (uint32_t)(row * (SAH * 2) + c * 16), Ap + (size_t)row * K + c * 8);
        }
#pragma unroll
        for (int i = 0; i < 4; i++) {   // B: 128 rows x 8 chunks of 16B
            int idx = tid + i * 256;
            int row = idx >> 3, c = idx & 7;
            cp16(bB + (uint32_t)(row * (SAH * 2) + c * 16), Bp + (size_t)row * K + c * 8);
        }
    };

    uint32_t af[2][4][4], bf[2][8][2];

    auto load_frags = [&](int buf, uint32_t sA, uint32_t sB, int ks) {
#pragma unroll
        for (int i = 0; i < 4; i++) {
            uint32_t addr = sA + (uint32_t)(((wm + i * 16 + (lane & 15)) * SAH
                              + ks * 16 + ((lane >> 4) << 3)) * 2);
            ldsm_x4(af[buf][i][0], af[buf][i][1], af[buf][i][2], af[buf][i][3], addr);
        }
#pragma unroll
        for (int p = 0; p < 4; p++) {
            uint32_t addr = sB + (uint32_t)(((wn + p * 16 + ((lane >> 4) << 3) + (lane & 7)) * SAH
                              + ks * 16 + (lane & 8)) * 2);
            ldsm_x4(bf[buf][2 * p][0], bf[buf][2 * p][1],
                    bf[buf][2 * p + 1][0], bf[buf][2 * p + 1][1], addr);
        }
    };

    // prologue
    load_stage(0, 0); cp_commit();
    if (KI > 1) load_stage(1, 1);
    cp_commit();

    for (int k = 0; k < KI; k++) {
        cp_wait<1>();
        __syncthreads();
        if (k + 2 < KI) load_stage((k + 2) % 3, k + 2);
        cp_commit();

        const uint32_t sA = sbase + (k % 3) * STG_BYTES;
        const uint32_t sB = sA + A_ST;
        load_frags(0, sA, sB, 0);
#pragma unroll
        for (int ks = 0; ks < 4; ks++) {
            if (ks < 3) load_frags((ks + 1) & 1, sA, sB, ks + 1);
            const int cb = ks & 1;
#pragma unroll
            for (int i = 0; i < 4; i++)
#pragma unroll
                for (int j = 0; j < 8; j++)
                    mma16816(acc[i][j], af[cb][i], bf[cb][j]);
        }
    }
    cp_wait<0>();

    // ---------------- register epilogue ----------------
#pragma unroll
    for (int i = 0; i < 4; i++) {
#pragma unroll
        for (int j = 0; j < 8; j++) {
            int row = m0 + wm + i * 16 + (lane >> 2);
            int col = n0 + wn + j * 8 + (lane & 3) * 2;
            float s0 = __ldg(scale + col), s1 = __ldg(scale + col + 1);
            if (MODE == 0) {
                float g0 = __ldg(signs + col), g1 = __ldg(signs + col + 1);
                float v00 = gelu_f(acc[i][j][0] * s0) * g0;
                float v01 = gelu_f(acc[i][j][1] * s1) * g1;
                float v10 = gelu_f(acc[i][j][2] * s0) * g0;
                float v11 = gelu_f(acc[i][j][3] * s1) * g1;
                __half* o = (__half*)Out;
                *(__half2*)(o + (size_t)row * Nfull + col) = __floats2half2_rn(v00, v01);
                *(__half2*)(o + (size_t)(row + 8) * Nfull + col) = __floats2half2_rn(v10, v11);
            } else {
                float* o = (float*)Out;
                *(float2*)(o + (size_t)row * Nfull + col) =
                    make_float2(acc[i][j][0] * s0, acc[i][j][1] * s1);
                *(float2*)(o + (size_t)(row + 8) * Nfull + col) =
                    make_float2(acc[i][j][2] * s0, acc[i][j][3] * s1);
            }
        }
    }
}

// ================= host =================
extern "C" void kernel_launch(void* const* d_in, const int* in_sizes, int n_in,
                              void* d_out, int out_size) {
    const float* x          = (const float*)d_in[0];
    const float* up_wq      = (const float*)d_in[1];
    const float* up_scale   = (const float*)d_in[2];
    const float* down_wq    = (const float*)d_in[3];
    const float* down_scale = (const float*)d_in[4];
    const float* up_signs   = (const float*)d_in[5];
    const float* down_signs = (const float*)d_in[6];

    __half *pXS, *pW1, *pW2, *pAR;
    { void* p; cudaGetSymbolAddress(&p, g_XS); pXS = (__half*)p; }
    { void* p; cudaGetSymbolAddress(&p, g_W1); pW1 = (__half*)p; }
    { void* p; cudaGetSymbolAddress(&p, g_W2); pW2 = (__half*)p; }
    { void* p; cudaGetSymbolAddress(&p, g_AR); pAR = (__half*)p; }

    cudaFuncSetAttribute(gemm_mma<0>, cudaFuncAttributeMaxDynamicSharedMemorySize, DYN_SMEM);
    cudaFuncSetAttribute(gemm_mma<1>, cudaFuncAttributeMaxDynamicSharedMemorySize, DYN_SMEM);

    // 1) fold Hadamard into weights: W1' = W1*H, W2' = W2*H (fp16)
    fwht_w_kernel<<<(D_MID * D_IN / 128) / 8, 256>>>(up_wq, pW1);
    fwht_w_kernel<<<(D_OUT * D_MID / 128) / 8, 256>>>(down_wq, pW2);

    // 2) XS = x * up_signs (fp16)
    xs_kernel<<<(T_ROWS * D_IN / 4) / 256, 256>>>(x, up_signs, pXS);

    // 3) GEMM1: h = XS @ W1'^T ; epilogue gelu(h*up_scale)*down_signs -> AR fp16
    {
        dim3 grid(D_MID / BN, T_ROWS / BM);  // (32, 64)
        gemm_mma<0><<<grid, 256, DYN_SMEM>>>(pXS, pW1, up_scale, down_signs, pAR,
                                             T_ROWS, D_MID, D_IN);
    }

    // 4) GEMM2: out = AR @ W2'^T ; epilogue *down_scale -> fp32
    {
        dim3 grid(D_OUT / BN, T_ROWS / BM);  // (8, 64)
        gemm_mma<1><<<grid, 256, DYN_SMEM>>>(pAR, pW2, down_scale, nullptr, d_out,
                                             T_ROWS, D_OUT, D_MID);
    }
}

// round 8
// speedup vs baseline: 2.6674x; 1.1345x over previous
#include <cuda_runtime.h>
#include <cuda_fp16.h>
#include <cstdint>

#define T_ROWS 16384
#define D_IN   1024
#define D_MID  4096
#define D_OUT  1024

// GEMM tiling: 128x128 CTA tile, 4 warps (2x2) of 64x64, 2 CTAs/SM
#define BM 128
#define BN 128
#define BK 64
#define STAGES 3
#define SAH 72                     // smem row stride in halves (144B): conflict-free ldsm
#define A_ST (BM * SAH * 2)        // 18432 B
#define B_ST (BN * SAH * 2)        // 18432 B
#define STG_BYTES (A_ST + B_ST)    // 36864 B
#define DYN_SMEM (STAGES * STG_BYTES + 128)   // 110720 B -> 2 CTAs per SM

// -------- scratch (static device globals; no allocs allowed) --------
__device__ __half g_XS[(size_t)T_ROWS * D_IN];    // x * up_signs, fp16
__device__ __half g_W1[(size_t)D_MID * D_IN];     // up_wq * H (blockwise), fp16
__device__ __half g_W2[(size_t)D_OUT * D_MID];    // down_wq * H (blockwise), fp16
__device__ __half g_AR[(size_t)T_ROWS * D_MID];   // gelu(h)*down_signs, fp16

// ---------------- helpers ----------------
static __device__ __forceinline__ uint32_t s2u(const void* p) {
    return (uint32_t)__cvta_generic_to_shared(p);
}
static __device__ __forceinline__ void cp16(uint32_t dst, const void* src) {
    asm volatile("cp.async.cg.shared.global [%0], [%1], 16;" :: "r"(dst), "l"(src));
}
static __device__ __forceinline__ void cp_commit() { asm volatile("cp.async.commit_group;" ::: "memory"); }
template <int N>
static __device__ __forceinline__ void cp_wait() { asm volatile("cp.async.wait_group %0;" :: "n"(N) : "memory"); }

static __device__ __forceinline__ void ldsm_x4(uint32_t& r0, uint32_t& r1, uint32_t& r2, uint32_t& r3,
                                               uint32_t addr) {
    asm volatile("ldmatrix.sync.aligned.m8n8.x4.shared.b16 {%0,%1,%2,%3}, [%4];"
                 : "=r"(r0), "=r"(r1), "=r"(r2), "=r"(r3) : "r"(addr));
}
static __device__ __forceinline__ void mma16816(float* c, const uint32_t* a, const uint32_t* b) {
    asm volatile(
        "mma.sync.aligned.m16n8k16.row.col.f32.f16.f16.f32 "
        "{%0,%1,%2,%3}, {%4,%5,%6,%7}, {%8,%9}, {%0,%1,%2,%3};"
        : "+f"(c[0]), "+f"(c[1]), "+f"(c[2]), "+f"(c[3])
        : "r"(a[0]), "r"(a[1]), "r"(a[2]), "r"(a[3]), "r"(b[0]), "r"(b[1]));
}
static __device__ __forceinline__ float gelu_f(float v) {
    float t = 1.5957691216057308f * (v + 0.044715f * v * v * v);
    return v * (1.0f / (1.0f + __expf(-t)));
}

// -------- W' = W * H (blockwise FWHT along contiguous dim), fp32 -> fp16 --------
__global__ void fwht_w_kernel(const float* __restrict__ w, __half* __restrict__ out) {
    int warp = blockIdx.x * 8 + (threadIdx.x >> 5);
    int lane = threadIdx.x & 31;
    size_t base = (size_t)warp * 128;
    float v[4];
#pragma unroll
    for (int j = 0; j < 4; j++) v[j] = w[base + lane + 32 * j];
#pragma unroll
    for (int len = 1; len <= 16; len <<= 1) {
#pragma unroll
        for (int j = 0; j < 4; j++) {
            float o = __shfl_xor_sync(0xffffffffu, v[j], len);
            v[j] = (lane & len) ? (o - v[j]) : (v[j] + o);
        }
    }
    float t0 = v[0] + v[1], t1 = v[0] - v[1], t2 = v[2] + v[3], t3 = v[2] - v[3];
    v[0] = t0 + t2; v[2] = t0 - t2; v[1] = t1 + t3; v[3] = t1 - t3;
    const float nrm = 0.08838834764831845f;
#pragma unroll
    for (int j = 0; j < 4; j++)
        out[base + lane + 32 * j] = __float2half(v[j] * nrm);
}

// -------- XS = x * up_signs, fp32 -> fp16 (vectorized) --------
__global__ void xs_kernel(const float* __restrict__ x, const float* __restrict__ signs,
                          __half* __restrict__ out) {
    int i = blockIdx.x * blockDim.x + threadIdx.x;   // one float4 per thread
    float4 v = reinterpret_cast<const float4*>(x)[i];
    int col = (i * 4) & (D_IN - 1);
    float4 s = *reinterpret_cast<const float4*>(signs + col);
    __half2 h0 = __floats2half2_rn(v.x * s.x, v.y * s.y);
    __half2 h1 = __floats2half2_rn(v.z * s.z, v.w * s.w);
    reinterpret_cast<__half2*>(out)[2 * i]     = h0;
    reinterpret_cast<__half2*>(out)[2 * i + 1] = h1;
}

// ================= HMMA GEMM =================
// C[m,n] = sum_k A[m,k]*B[n,k]; A:[M,K], B:[N,K] fp16 K-major.
// 128 threads, warp grid 2(M)x2(N), warp tile 64x64, mma.m16n8k16, BK=64,
// double-buffered register fragments, 2 CTAs/SM.
// MODE 0: out fp16 = gelu(acc*scale[n]) * signs[n]
// MODE 1: out fp32 = acc*scale[n]
template <int MODE>
__global__ __launch_bounds__(128, 2)
void gemm_mma(const __half* __restrict__ A, const __half* __restrict__ B,
              const float* __restrict__ scale, const float* __restrict__ signs,
              void* __restrict__ Out, int M, int Nfull, int K) {
    extern __shared__ char dsm_raw[];
    char* sb = (char*)((((uintptr_t)dsm_raw) + 127) & ~(uintptr_t)127);
    const uint32_t sbase = s2u(sb);

    const int tid = threadIdx.x;
    const int wid = tid >> 5;
    const int lane = tid & 31;
    const int wm = (wid >> 1) * 64;   // 2 warps along M
    const int wn = (wid & 1) * 64;    // 2 warps along N
    const int m0 = blockIdx.y * BM;
    const int n0 = blockIdx.x * BN;
    const int KI = K / BK;

    float acc[4][8][4];
#pragma unroll
    for (int i = 0; i < 4; i++)
#pragma unroll
        for (int j = 0; j < 8; j++)
#pragma unroll
            for (int e = 0; e < 4; e++) acc[i][j][e] = 0.0f;

    auto load_stage = [&](int s, int kk) {
        const int k0 = kk * BK;
        uint32_t aB = sbase + s * STG_BYTES;
        uint32_t bB = aB + A_ST;
        const __half* Ap = A + (size_t)m0 * K + k0;
        const __half* Bp = B + (size_t)n0 * K + k0;
#pragma unroll
        for (int i = 0; i < 8; i++) {   // A: 128 rows x 8 chunks of 16B
            int idx = tid + i * 128;
            int row = idx >> 3, c = idx & 7;
            cp16(aB + (uint32_t)(row * (SAH * 2) + c * 16), Ap + (size_t)row * K + c * 8);
        }
#pragma unroll
        for (int i = 0; i < 8; i++) {   // B: 128 rows x 8 chunks of 16B
            int idx = tid + i * 128;
            int row = idx >> 3, c = idx & 7;
            cp16(bB + (uint32_t)(row * (SAH * 2) + c * 16), Bp + (size_t)row * K + c * 8);
        }
    };

    uint32_t af[2][4][4], bf[2][8][2];

    auto load_frags = [&](int buf, uint32_t sA, uint32_t sB, int ks) {
#pragma unroll
        for (int i = 0; i < 4; i++) {
            uint32_t addr = sA + (uint32_t)(((wm + i * 16 + (lane & 15)) * SAH
                              + ks * 16 + ((lane >> 4) << 3)) * 2);
            ldsm_x4(af[buf][i][0], af[buf][i][1], af[buf][i][2], af[buf][i][3], addr);
        }
#pragma unroll
        for (int p = 0; p < 4; p++) {
            uint32_t addr = sB + (uint32_t)(((wn + p * 16 + ((lane >> 4) << 3) + (lane & 7)) * SAH
                              + ks * 16 + (lane & 8)) * 2);
            ldsm_x4(bf[buf][2 * p][0], bf[buf][2 * p][1],
                    bf[buf][2 * p + 1][0], bf[buf][2 * p + 1][1], addr);
        }
    };

    // prologue
    load_stage(0, 0); cp_commit();
    if (KI > 1) load_stage(1, 1);
    cp_commit();

    for (int k = 0; k < KI; k++) {
        cp_wait<1>();
        __syncthreads();
        if (k + 2 < KI) load_stage((k + 2) % 3, k + 2);
        cp_commit();

        const uint32_t sA = sbase + (k % 3) * STG_BYTES;
        const uint32_t sB = sA + A_ST;
        load_frags(0, sA, sB, 0);
#pragma unroll
        for (int ks = 0; ks < 4; ks++) {
            if (ks < 3) load_frags((ks + 1) & 1, sA, sB, ks + 1);
            const int cb = ks & 1;
#pragma unroll
            for (int i = 0; i < 4; i++)
#pragma unroll
                for (int j = 0; j < 8; j++)
                    mma16816(acc[i][j], af[cb][i], bf[cb][j]);
        }
    }
    cp_wait<0>();

    // ---------------- register epilogue ----------------
#pragma unroll
    for (int i = 0; i < 4; i++) {
#pragma unroll
        for (int j = 0; j < 8; j++) {
            int row = m0 + wm + i * 16 + (lane >> 2);
            int col = n0 + wn + j * 8 + (lane & 3) * 2;
            float s0 = __ldg(scale + col), s1 = __ldg(scale + col + 1);
            if (MODE == 0) {
                float g0 = __ldg(signs + col), g1 = __ldg(signs + col + 1);
                float v00 = gelu_f(acc[i][j][0] * s0) * g0;
                float v01 = gelu_f(acc[i][j][1] * s1) * g1;
                float v10 = gelu_f(acc[i][j][2] * s0) * g0;
                float v11 = gelu_f(acc[i][j][3] * s1) * g1;
                __half* o = (__half*)Out;
                *(__half2*)(o + (size_t)row * Nfull + col) = __floats2half2_rn(v00, v01);
                *(__half2*)(o + (size_t)(row + 8) * Nfull + col) = __floats2half2_rn(v10, v11);
            } else {
                float* o = (float*)Out;
                *(float2*)(o + (size_t)row * Nfull + col) =
                    make_float2(acc[i][j][0] * s0, acc[i][j][1] * s1);
                *(float2*)(o + (size_t)(row + 8) * Nfull + col) =
                    make_float2(acc[i][j][2] * s0, acc[i][j][3] * s1);
            }
        }
    }
}

// ================= host =================
extern "C" void kernel_launch(void* const* d_in, const int* in_sizes, int n_in,
                              void* d_out, int out_size) {
    const float* x          = (const float*)d_in[0];
    const float* up_wq      = (const float*)d_in[1];
    const float* up_scale   = (const float*)d_in[2];
    const float* down_wq    = (const float*)d_in[3];
    const float* down_scale = (const float*)d_in[4];
    const float* up_signs   = (const float*)d_in[5];
    const float* down_signs = (const float*)d_in[6];

    __half *pXS, *pW1, *pW2, *pAR;
    { void* p; cudaGetSymbolAddress(&p, g_XS); pXS = (__half*)p; }
    { void* p; cudaGetSymbolAddress(&p, g_W1); pW1 = (__half*)p; }
    { void* p; cudaGetSymbolAddress(&p, g_W2); pW2 = (__half*)p; }
    { void* p; cudaGetSymbolAddress(&p, g_AR); pAR = (__half*)p; }

    cudaFuncSetAttribute(gemm_mma<0>, cudaFuncAttributeMaxDynamicSharedMemorySize, DYN_SMEM);
    cudaFuncSetAttribute(gemm_mma<1>, cudaFuncAttributeMaxDynamicSharedMemorySize, DYN_SMEM);

    // 1) fold Hadamard into weights: W1' = W1*H, W2' = W2*H (fp16)
    fwht_w_kernel<<<(D_MID * D_IN / 128) / 8, 256>>>(up_wq, pW1);
    fwht_w_kernel<<<(D_OUT * D_MID / 128) / 8, 256>>>(down_wq, pW2);

    // 2) XS = x * up_signs (fp16)
    xs_kernel<<<(T_ROWS * D_IN / 4) / 256, 256>>>(x, up_signs, pXS);

    // 3) GEMM1: h = XS @ W1'^T ; epilogue gelu(h*up_scale)*down_signs -> AR fp16
    {
        dim3 grid(D_MID / BN, T_ROWS / BM);  // (32, 128)
        gemm_mma<0><<<grid, 128, DYN_SMEM>>>(pXS, pW1, up_scale, down_signs, pAR,
                                             T_ROWS, D_MID, D_IN);
    }

    // 4) GEMM2: out = AR @ W2'^T ; epilogue *down_scale -> fp32
    {
        dim3 grid(D_OUT / BN, T_ROWS / BM);  // (8, 128)
        gemm_mma<1><<<grid, 128, DYN_SMEM>>>(pAR, pW2, down_scale, nullptr, d_out,
                                             T_ROWS, D_OUT, D_MID);
    }
}

// round 9
// speedup vs baseline: 2.9399x; 1.1022x over previous
#include <cuda_runtime.h>
#include <cuda_fp16.h>
#include <cstdint>

#define T_ROWS 16384
#define D_IN   1024
#define D_MID  4096
#define D_OUT  1024

// GEMM tiling: 128x128 CTA tile, 8 warps (2Mx4N) of 64x32, 2 CTAs/SM
#define BM 128
#define BN 128
#define BK 64
#define STAGES 3
#define SAH 72                     // smem row stride in halves (144B): conflict-free ldsm
#define A_ST (BM * SAH * 2)        // 18432 B
#define B_ST (BN * SAH * 2)        // 18432 B
#define STG_BYTES (A_ST + B_ST)    // 36864 B
#define DYN_SMEM (STAGES * STG_BYTES + 128)   // 110720 B -> 2 CTAs per SM

// -------- scratch (static device globals; no allocs allowed) --------
__device__ __half g_XS[(size_t)T_ROWS * D_IN];    // x * up_signs, fp16
__device__ __half g_W1[(size_t)D_MID * D_IN];     // up_wq * H (blockwise), fp16
__device__ __half g_W2[(size_t)D_OUT * D_MID];    // down_wq * H (blockwise), fp16
__device__ __half g_AR[(size_t)T_ROWS * D_MID];   // gelu(h)*down_signs, fp16

// ---------------- helpers ----------------
static __device__ __forceinline__ uint32_t s2u(const void* p) {
    return (uint32_t)__cvta_generic_to_shared(p);
}
static __device__ __forceinline__ void cp16(uint32_t dst, const void* src) {
    asm volatile("cp.async.cg.shared.global [%0], [%1], 16;" :: "r"(dst), "l"(src));
}
static __device__ __forceinline__ void cp_commit() { asm volatile("cp.async.commit_group;" ::: "memory"); }
template <int N>
static __device__ __forceinline__ void cp_wait() { asm volatile("cp.async.wait_group %0;" :: "n"(N) : "memory"); }

static __device__ __forceinline__ void ldsm_x4(uint32_t& r0, uint32_t& r1, uint32_t& r2, uint32_t& r3,
                                               uint32_t addr) {
    asm volatile("ldmatrix.sync.aligned.m8n8.x4.shared.b16 {%0,%1,%2,%3}, [%4];"
                 : "=r"(r0), "=r"(r1), "=r"(r2), "=r"(r3) : "r"(addr));
}
static __device__ __forceinline__ void mma16816(float* c, const uint32_t* a, const uint32_t* b) {
    asm volatile(
        "mma.sync.aligned.m16n8k16.row.col.f32.f16.f16.f32 "
        "{%0,%1,%2,%3}, {%4,%5,%6,%7}, {%8,%9}, {%0,%1,%2,%3};"
        : "+f"(c[0]), "+f"(c[1]), "+f"(c[2]), "+f"(c[3])
        : "r"(a[0]), "r"(a[1]), "r"(a[2]), "r"(a[3]), "r"(b[0]), "r"(b[1]));
}
static __device__ __forceinline__ float gelu_f(float v) {
    float t = 1.5957691216057308f * (v + 0.044715f * v * v * v);
    return v * (1.0f / (1.0f + __expf(-t)));
}

// -------- W' = W * H (blockwise FWHT along contiguous dim), fp32 -> fp16 --------
__global__ void fwht_w_kernel(const float* __restrict__ w, __half* __restrict__ out) {
    int warp = blockIdx.x * 8 + (threadIdx.x >> 5);
    int lane = threadIdx.x & 31;
    size_t base = (size_t)warp * 128;
    float v[4];
#pragma unroll
    for (int j = 0; j < 4; j++) v[j] = w[base + lane + 32 * j];
#pragma unroll
    for (int len = 1; len <= 16; len <<= 1) {
#pragma unroll
        for (int j = 0; j < 4; j++) {
            float o = __shfl_xor_sync(0xffffffffu, v[j], len);
            v[j] = (lane & len) ? (o - v[j]) : (v[j] + o);
        }
    }
    float t0 = v[0] + v[1], t1 = v[0] - v[1], t2 = v[2] + v[3], t3 = v[2] - v[3];
    v[0] = t0 + t2; v[2] = t0 - t2; v[1] = t1 + t3; v[3] = t1 - t3;
    const float nrm = 0.08838834764831845f;
#pragma unroll
    for (int j = 0; j < 4; j++)
        out[base + lane + 32 * j] = __float2half(v[j] * nrm);
}

// -------- XS = x * up_signs, fp32 -> fp16 (vectorized) --------
__global__ void xs_kernel(const float* __restrict__ x, const float* __restrict__ signs,
                          __half* __restrict__ out) {
    int i = blockIdx.x * blockDim.x + threadIdx.x;   // one float4 per thread
    float4 v = reinterpret_cast<const float4*>(x)[i];
    int col = (i * 4) & (D_IN - 1);
    float4 s = *reinterpret_cast<const float4*>(signs + col);
    __half2 h0 = __floats2half2_rn(v.x * s.x, v.y * s.y);
    __half2 h1 = __floats2half2_rn(v.z * s.z, v.w * s.w);
    reinterpret_cast<__half2*>(out)[2 * i]     = h0;
    reinterpret_cast<__half2*>(out)[2 * i + 1] = h1;
}

// ================= HMMA GEMM =================
// C[m,n] = sum_k A[m,k]*B[n,k]; A:[M,K], B:[N,K] fp16 K-major.
// 256 threads, warp grid 2(M)x4(N), warp tile 64x32, mma.m16n8k16, BK=64,
// single-buffered register fragments (latency hidden by 16 warps/SM), 2 CTAs/SM.
// MODE 0: out fp16 = gelu(acc*scale[n]) * signs[n]
// MODE 1: out fp32 = acc*scale[n]
template <int MODE>
__global__ __launch_bounds__(256, 2)
void gemm_mma(const __half* __restrict__ A, const __half* __restrict__ B,
              const float* __restrict__ scale, const float* __restrict__ signs,
              void* __restrict__ Out, int M, int Nfull, int K) {
    extern __shared__ char dsm_raw[];
    char* sb = (char*)((((uintptr_t)dsm_raw) + 127) & ~(uintptr_t)127);
    const uint32_t sbase = s2u(sb);

    const int tid = threadIdx.x;
    const int wid = tid >> 5;
    const int lane = tid & 31;
    const int wm = (wid >> 2) * 64;   // 2 warps along M
    const int wn = (wid & 3) * 32;    // 4 warps along N
    const int m0 = blockIdx.y * BM;
    const int n0 = blockIdx.x * BN;
    const int KI = K / BK;

    float acc[4][4][4];
#pragma unroll
    for (int i = 0; i < 4; i++)
#pragma unroll
        for (int j = 0; j < 4; j++)
#pragma unroll
            for (int e = 0; e < 4; e++) acc[i][j][e] = 0.0f;

    auto load_stage = [&](int s, int kk) {
        const int k0 = kk * BK;
        uint32_t aB = sbase + s * STG_BYTES;
        uint32_t bB = aB + A_ST;
        const __half* Ap = A + (size_t)m0 * K + k0;
        const __half* Bp = B + (size_t)n0 * K + k0;
#pragma unroll
        for (int i = 0; i < 4; i++) {   // A: 128 rows x 8 chunks of 16B = 1024
            int idx = tid + i * 256;
            int row = idx >> 3, c = idx & 7;
            cp16(aB + (uint32_t)(row * (SAH * 2) + c * 16), Ap + (size_t)row * K + c * 8);
        }
#pragma unroll
        for (int i = 0; i < 4; i++) {   // B: 128 rows x 8 chunks of 16B = 1024
            int idx = tid + i * 256;
            int row = idx >> 3, c = idx & 7;
            cp16(bB + (uint32_t)(row * (SAH * 2) + c * 16), Bp + (size_t)row * K + c * 8);
        }
    };

    // prologue
    load_stage(0, 0); cp_commit();
    if (KI > 1) load_stage(1, 1);
    cp_commit();

    for (int k = 0; k < KI; k++) {
        cp_wait<1>();
        __syncthreads();
        if (k + 2 < KI) load_stage((k + 2) % 3, k + 2);
        cp_commit();

        const uint32_t sA = sbase + (k % 3) * STG_BYTES;
        const uint32_t sB = sA + A_ST;
#pragma unroll
        for (int ks = 0; ks < 4; ks++) {
            uint32_t af[4][4], bf[4][2];
#pragma unroll
            for (int i = 0; i < 4; i++) {
                uint32_t addr = sA + (uint32_t)(((wm + i * 16 + (lane & 15)) * SAH
                                  + ks * 16 + ((lane >> 4) << 3)) * 2);
                ldsm_x4(af[i][0], af[i][1], af[i][2], af[i][3], addr);
            }
#pragma unroll
            for (int p = 0; p < 2; p++) {
                uint32_t addr = sB + (uint32_t)(((wn + p * 16 + ((lane >> 4) << 3) + (lane & 7)) * SAH
                                  + ks * 16 + (lane & 8)) * 2);
                ldsm_x4(bf[2 * p][0], bf[2 * p][1], bf[2 * p + 1][0], bf[2 * p + 1][1], addr);
            }
#pragma unroll
            for (int i = 0; i < 4; i++)
#pragma unroll
                for (int j = 0; j < 4; j++)
                    mma16816(acc[i][j], af[i], bf[j]);
        }
    }
    cp_wait<0>();

    // ---------------- register epilogue ----------------
#pragma unroll
    for (int i = 0; i < 4; i++) {
#pragma unroll
        for (int j = 0; j < 4; j++) {
            int row = m0 + wm + i * 16 + (lane >> 2);
            int col = n0 + wn + j * 8 + (lane & 3) * 2;
            float s0 = __ldg(scale + col), s1 = __ldg(scale + col + 1);
            if (MODE == 0) {
                float g0 = __ldg(signs + col), g1 = __ldg(signs + col + 1);
                float v00 = gelu_f(acc[i][j][0] * s0) * g0;
                float v01 = gelu_f(acc[i][j][1] * s1) * g1;
                float v10 = gelu_f(acc[i][j][2] * s0) * g0;
                float v11 = gelu_f(acc[i][j][3] * s1) * g1;
                __half* o = (__half*)Out;
                *(__half2*)(o + (size_t)row * Nfull + col) = __floats2half2_rn(v00, v01);
                *(__half2*)(o + (size_t)(row + 8) * Nfull + col) = __floats2half2_rn(v10, v11);
            } else {
                float* o = (float*)Out;
                *(float2*)(o + (size_t)row * Nfull + col) =
                    make_float2(acc[i][j][0] * s0, acc[i][j][1] * s1);
                *(float2*)(o + (size_t)(row + 8) * Nfull + col) =
                    make_float2(acc[i][j][2] * s0, acc[i][j][3] * s1);
            }
        }
    }
}

// ================= host =================
extern "C" void kernel_launch(void* const* d_in, const int* in_sizes, int n_in,
                              void* d_out, int out_size) {
    const float* x          = (const float*)d_in[0];
    const float* up_wq      = (const float*)d_in[1];
    const float* up_scale   = (const float*)d_in[2];
    const float* down_wq    = (const float*)d_in[3];
    const float* down_scale = (const float*)d_in[4];
    const float* up_signs   = (const float*)d_in[5];
    const float* down_signs = (const float*)d_in[6];

    __half *pXS, *pW1, *pW2, *pAR;
    { void* p; cudaGetSymbolAddress(&p, g_XS); pXS = (__half*)p; }
    { void* p; cudaGetSymbolAddress(&p, g_W1); pW1 = (__half*)p; }
    { void* p; cudaGetSymbolAddress(&p, g_W2); pW2 = (__half*)p; }
    { void* p; cudaGetSymbolAddress(&p, g_AR); pAR = (__half*)p; }

    cudaFuncSetAttribute(gemm_mma<0>, cudaFuncAttributeMaxDynamicSharedMemorySize, DYN_SMEM);
    cudaFuncSetAttribute(gemm_mma<1>, cudaFuncAttributeMaxDynamicSharedMemorySize, DYN_SMEM);

    // 1) fold Hadamard into weights: W1' = W1*H, W2' = W2*H (fp16)
    fwht_w_kernel<<<(D_MID * D_IN / 128) / 8, 256>>>(up_wq, pW1);
    fwht_w_kernel<<<(D_OUT * D_MID / 128) / 8, 256>>>(down_wq, pW2);

    // 2) XS = x * up_signs (fp16)
    xs_kernel<<<(T_ROWS * D_IN / 4) / 256, 256>>>(x, up_signs, pXS);

    // 3) GEMM1: h = XS @ W1'^T ; epilogue gelu(h*up_scale)*down_signs -> AR fp16
    {
        dim3 grid(D_MID / BN, T_ROWS / BM);  // (32, 128)
        gemm_mma<0><<<grid, 256, DYN_SMEM>>>(pXS, pW1, up_scale, down_signs, pAR,
                                             T_ROWS, D_MID, D_IN);
    }

    // 4) GEMM2: out = AR @ W2'^T ; epilogue *down_scale -> fp32
    {
        dim3 grid(D_OUT / BN, T_ROWS / BM);  // (8, 128)
        gemm_mma<1><<<grid, 256, DYN_SMEM>>>(pAR, pW2, down_scale, nullptr, d_out,
                                             T_ROWS, D_OUT, D_MID);
    }
}